// round 3
// baseline (speedup 1.0000x reference)
#include <cuda_runtime.h>
#include <cuda_bf16.h>
#include <cstdint>
#include <cstddef>

// Problem constants
#define T_STEPS 1024
#define BATCH   64
#define DIM     512
#define HID     512
#define DH      1024          // D + H
#define G4      2048          // 4*H
#define MROWS   (T_STEPS * BATCH)   // 65536

// Phase-2 partitioning
#define NGROUPS 4
#define CPG     32            // CTAs per group
#define NCTA    128
#define BPG     16            // batches per group
#define JPC     16            // hidden units per CTA
#define RPC     64            // weight rows per CTA (4 gates * JPC)
#define KP      516           // padded smem row stride (floats)

// ---------------- device scratch (static allocations only) ----------------
__device__ float         g_zx[(size_t)MROWS * G4];      // 512 MB precomputed x-part + bias
__device__ float         g_h[2][BATCH][HID];            // double-buffered hidden state
__device__ unsigned      g_cnt[NGROUPS];                // per-group barrier counters
__device__ __nv_bfloat16 g_xh[(size_t)MROWS * 512];     // X split hi
__device__ __nv_bfloat16 g_xl[(size_t)MROWS * 512];     // X split lo
__device__ __nv_bfloat16 g_wxh[(size_t)G4 * 512];       // W x-part split hi (gate-major rows)
__device__ __nv_bfloat16 g_wxl[(size_t)G4 * 512];       // W x-part split lo
__device__ float         g_ball[G4];                    // packed biases

__device__ __forceinline__ unsigned ld_acq(unsigned* p) {
    unsigned v;
    asm volatile("ld.acquire.gpu.u32 %0, [%1];" : "=r"(v) : "l"(p) : "memory");
    return v;
}

// ---------------- PTX helpers (sm_80-class, base-target legal) ----------------
__device__ __forceinline__ uint32_t smem_u32(const void* p) {
    uint32_t a;
    asm("{ .reg .u64 t; cvta.to.shared.u64 t, %1; cvt.u32.u64 %0, t; }" : "=r"(a) : "l"(p));
    return a;
}
__device__ __forceinline__ void cp16(uint32_t dst, const void* src) {
    asm volatile("cp.async.cg.shared.global [%0], [%1], 16;" :: "r"(dst), "l"(src));
}
__device__ __forceinline__ void cp_commit() { asm volatile("cp.async.commit_group;" ::: "memory"); }
template <int N> __device__ __forceinline__ void cp_wait() {
    asm volatile("cp.async.wait_group %0;" :: "n"(N) : "memory");
}
__device__ __forceinline__ void ldsm4(uint32_t* r, uint32_t addr) {
    asm volatile("ldmatrix.sync.aligned.m8n8.x4.shared.b16 {%0,%1,%2,%3}, [%4];"
        : "=r"(r[0]), "=r"(r[1]), "=r"(r[2]), "=r"(r[3]) : "r"(addr));
}
__device__ __forceinline__ void mma16816(float* d, const uint32_t* a, uint32_t b0, uint32_t b1) {
    asm volatile("mma.sync.aligned.m16n8k16.row.col.f32.bf16.bf16.f32 "
        "{%0,%1,%2,%3}, {%4,%5,%6,%7}, {%8,%9}, {%0,%1,%2,%3};"
        : "+f"(d[0]), "+f"(d[1]), "+f"(d[2]), "+f"(d[3])
        : "r"(a[0]), "r"(a[1]), "r"(a[2]), "r"(a[3]), "r"(b0), "r"(b1));
}

// =======================================================================
// Pre-pass: split X and W x-part into bf16 hi/lo; pack biases.
// =======================================================================
__global__ __launch_bounds__(256) void split_k(
    const float* __restrict__ X,
    const float* __restrict__ Wf, const float* __restrict__ Wi,
    const float* __restrict__ Wg, const float* __restrict__ Wo,
    const float* __restrict__ bf, const float* __restrict__ bi,
    const float* __restrict__ bg, const float* __restrict__ bo)
{
    const size_t stride = (size_t)gridDim.x * blockDim.x;
    size_t t0 = (size_t)blockIdx.x * blockDim.x + threadIdx.x;

    const size_t NX = (size_t)MROWS * 512;
    for (size_t i = t0; i < NX; i += stride) {
        float v = X[i];
        __nv_bfloat16 h = __float2bfloat16(v);
        g_xh[i] = h;
        g_xl[i] = __float2bfloat16(v - __bfloat162float(h));
    }
    const size_t NW = (size_t)G4 * 512;
    for (size_t i = t0; i < NW; i += stride) {
        int r = (int)(i >> 9), k = (int)(i & 511);
        int gate = r >> 9, j = r & 511;
        const float* wp = (gate == 0) ? Wf : (gate == 1) ? Wi : (gate == 2) ? Wg : Wo;
        float v = wp[(size_t)j * DH + k];
        __nv_bfloat16 h = __float2bfloat16(v);
        g_wxh[i] = h;
        g_wxl[i] = __float2bfloat16(v - __bfloat162float(h));
    }
    for (size_t i = t0; i < G4; i += stride) {
        int gate = (int)(i >> 9);
        const float* bp = (gate == 0) ? bf : (gate == 1) ? bi : (gate == 2) ? bg : bo;
        g_ball[i] = bp[i & 511];
    }
}

// =======================================================================
// Phase 1: mma.sync bf16x3 GEMM.  Zx[m][n] = X[m]·Wx[n] + b[n]
// CTA tile 128x128, warp tile 64x32, K chunks of 32, cp.async 2-stage.
// Smem tiles row-padded to 80B (conflict-free ldmatrix).
// =======================================================================
#define RSTR  80                 // bytes per 32-bf16 smem row
#define TILEB (128 * RSTR)       // 10240 bytes per operand tile
#define STAGE (4 * TILEB)        // 40960 per stage (Ah|Al|Bh|Bl)
#define SMEM_P1 (2 * STAGE)      // 81920

__global__ __launch_bounds__(256, 1) void p1_mma()
{
    extern __shared__ char sm[];
    const uint32_t smb = smem_u32(sm);

    const int tid = threadIdx.x, wid = tid >> 5, lane = tid & 31;
    const int n0 = blockIdx.x * 128;
    const int m0 = blockIdx.y * 128;
    const int wm = (wid >> 2) * 64;      // warp m offset (2 rows of warps)
    const int wn = (wid & 3) * 32;       // warp n offset (4 cols of warps)

    // ldmatrix per-lane address components
    const int g = lane >> 3, r = lane & 7;
    const uint32_t aoff = (uint32_t)(((g & 1) * 8 + r) * RSTR + (g >> 1) * 16);
    const uint32_t boff = (uint32_t)(((g >> 1) * 8 + r) * RSTR + (g & 1) * 16);

    float acc[4][4][4];
#pragma unroll
    for (int mt = 0; mt < 4; mt++)
#pragma unroll
        for (int nt = 0; nt < 4; nt++)
#pragma unroll
            for (int q = 0; q < 4; q++) acc[mt][nt][q] = 0.f;

    auto load_stage = [&](int kc, int s) {
        const uint32_t base = smb + s * STAGE;
        const int kc0 = kc * 32;
#pragma unroll
        for (int j = 0; j < 2; j++) {
            int lin = tid + j * 256;            // 0..511
            int row = lin >> 2, seg = lin & 3;
            uint32_t d = base + (uint32_t)(row * RSTR + seg * 16);
            size_t srcA = (size_t)(m0 + row) * 512 + kc0 + seg * 8;
            size_t srcB = (size_t)(n0 + row) * 512 + kc0 + seg * 8;
            cp16(d,             &g_xh[srcA]);
            cp16(d + TILEB,     &g_xl[srcA]);
            cp16(d + 2 * TILEB, &g_wxh[srcB]);
            cp16(d + 3 * TILEB, &g_wxl[srcB]);
        }
        cp_commit();
    };

    load_stage(0, 0);
    load_stage(1, 1);

    for (int kc = 0; kc < 16; kc++) {
        const int s = kc & 1;
        const uint32_t base = smb + s * STAGE;
        cp_wait<1>();
        __syncthreads();

#pragma unroll
        for (int ks = 0; ks < 2; ks++) {
            const uint32_t kb = ks * 32;
            uint32_t ah[4][4], al[4][4], bh[2][4], bl[2][4];
#pragma unroll
            for (int i = 0; i < 4; i++) {
                uint32_t arow = base + (uint32_t)((wm + 16 * i) * RSTR) + aoff + kb;
                ldsm4(ah[i], arow);
                ldsm4(al[i], arow + TILEB);
            }
#pragma unroll
            for (int p = 0; p < 2; p++) {
                uint32_t brow = base + 2 * TILEB + (uint32_t)((wn + 16 * p) * RSTR) + boff + kb;
                ldsm4(bh[p], brow);
                ldsm4(bl[p], brow + TILEB);
            }
#pragma unroll
            for (int mt = 0; mt < 4; mt++) {
#pragma unroll
                for (int nt = 0; nt < 4; nt++) {
                    const int p = nt >> 1, q2 = (nt & 1) * 2;
                    mma16816(acc[mt][nt], ah[mt], bh[p][q2], bh[p][q2 + 1]);
                    mma16816(acc[mt][nt], ah[mt], bl[p][q2], bl[p][q2 + 1]);
                    mma16816(acc[mt][nt], al[mt], bh[p][q2], bh[p][q2 + 1]);
                }
            }
        }
        __syncthreads();
        if (kc + 2 < 16) load_stage(kc + 2, s);
    }

    // ---- epilogue: +bias, direct global store (float2 per fragment half) ----
    const int cr = lane >> 2, cc = (lane & 3) * 2;
#pragma unroll
    for (int mt = 0; mt < 4; mt++) {
#pragma unroll
        for (int nt = 0; nt < 4; nt++) {
            const int grow = m0 + wm + 16 * mt + cr;
            const int gcol = n0 + wn + 8 * nt + cc;
            const float b0 = g_ball[gcol], b1 = g_ball[gcol + 1];
            float2 v0 = make_float2(acc[mt][nt][0] + b0, acc[mt][nt][1] + b1);
            float2 v1 = make_float2(acc[mt][nt][2] + b0, acc[mt][nt][3] + b1);
            *(float2*)&g_zx[(size_t)grow * G4 + gcol]       = v0;
            *(float2*)&g_zx[(size_t)(grow + 8) * G4 + gcol] = v1;
        }
    }
}

// =======================================================================
// Reset kernel: zero barrier counters and h0 (deterministic per replay)
// =======================================================================
__global__ void reset_k()
{
    int tid = threadIdx.x;
    if (tid < NGROUPS) g_cnt[tid] = 0;
    float* p = &g_h[0][0][0];
    for (int i = tid; i < BATCH * HID; i += 256) p[i] = 0.f;
}

// =======================================================================
// Phase 2: persistent sequential LSTM. 128 CTAs (4 groups x 32), 256 thr.
// =======================================================================
__global__ __launch_bounds__(256, 1) void lstm_seq(
    const float* __restrict__ Wf, const float* __restrict__ Wi,
    const float* __restrict__ Wg, const float* __restrict__ Wo,
    const float* __restrict__ q_scale, const float* __restrict__ q_bias,
    float* __restrict__ out)
{
    extern __shared__ float smf[];
    float* w_s = smf;                       // [64][KP]
    float* h_s = smf + RPC * KP;            // [16][KP]
    float* red = h_s + BPG * KP;            // [8][1024]
    float* c_s = red + 8 * 1024;            // [256]

    const int tid = threadIdx.x;
    const int cta = blockIdx.x;
    const int grp = cta >> 5;
    const int cig = cta & 31;
    const int b0  = grp * BPG;
    const int j0  = cig * JPC;

    for (int idx = tid; idx < RPC * 512; idx += 256) {
        int r = idx >> 9, k = idx & 511;
        int gate = r >> 4, jl_ = r & 15;
        const float* wp = (gate == 0) ? Wf : (gate == 1) ? Wi : (gate == 2) ? Wg : Wo;
        w_s[r * KP + k] = wp[(size_t)(j0 + jl_) * DH + 512 + k];
    }
    c_s[tid] = 0.f;

    const int jl = tid & 15, bl = tid >> 4;
    const int j = j0 + jl, b = b0 + bl;
    const float qs = q_scale[j], qb = q_bias[j];

    const int lane = tid & 31, wrp = tid >> 5;
    const int rL = lane & 7, bL = lane >> 3;
    const int kbase = wrp * 64;
    const int uB = bl >> 2, bLL = bl & 3;

    __syncthreads();

    for (int t = 0; t < T_STEPS; t++) {
        const float* hsrc = &g_h[t & 1][b0][0];
        for (int i = tid; i < BPG * 128; i += 256) {
            int row = i >> 7, c4 = i & 127;
            float4 v = __ldcg((const float4*)(hsrc + row * 512 + c4 * 4));
            *(float4*)&h_s[row * KP + c4 * 4] = v;
        }
        __syncthreads();

        float acc[4][8];
#pragma unroll
        for (int u = 0; u < 4; u++)
#pragma unroll
            for (int m = 0; m < 8; m++) acc[u][m] = 0.f;

#pragma unroll 4
        for (int kk = 0; kk < 64; kk += 4) {
            const int k = kbase + kk;
            float4 hf[4], wf[8];
#pragma unroll
            for (int u = 0; u < 4; u++)
                hf[u] = *(const float4*)&h_s[(bL + 4 * u) * KP + k];
#pragma unroll
            for (int m = 0; m < 8; m++)
                wf[m] = *(const float4*)&w_s[(rL + 8 * m) * KP + k];
#pragma unroll
            for (int u = 0; u < 4; u++)
#pragma unroll
                for (int m = 0; m < 8; m++) {
                    acc[u][m] += hf[u].x * wf[m].x;
                    acc[u][m] += hf[u].y * wf[m].y;
                    acc[u][m] += hf[u].z * wf[m].z;
                    acc[u][m] += hf[u].w * wf[m].w;
                }
        }

#pragma unroll
        for (int u = 0; u < 4; u++)
#pragma unroll
            for (int m = 0; m < 8; m++)
                red[wrp * 1024 + (u * 8 + m) * 32 + rL * 4 + bL] = acc[u][m];
        __syncthreads();

        float z[4];
#pragma unroll
        for (int gate = 0; gate < 4; gate++) {
            int r = gate * 16 + jl;
            int idx = (uB * 8 + (r >> 3)) * 32 + (r & 7) * 4 + bLL;
            float s = 0.f;
#pragma unroll
            for (int ww = 0; ww < 8; ww++) s += red[ww * 1024 + idx];
            z[gate] = s + g_zx[((size_t)(t * BATCH + b)) * G4 + gate * 512 + j];
        }

        float sf = 1.f / (1.f + expf(-z[0]));
        float si = 1.f / (1.f + expf(-z[1]));
        float sg = tanhf(z[2]);
        float so = 1.f / (1.f + expf(-z[3]));

        float fg = tanhf(sf * qs + qb);
        float ig = tanhf(si * qs + qb);
        float gg = tanhf(sg * qs + qb);
        float og = tanhf(so * qs + qb);

        float c = fg * c_s[tid] + ig * gg;
        c_s[tid] = c;
        float h = og * tanhf(c);

        g_h[(t + 1) & 1][b][j] = h;
        out[(size_t)t * (BATCH * HID) + b * HID + j] = h;
        if (t == T_STEPS - 1) {
            out[(size_t)T_STEPS * (BATCH * HID) + b * HID + j] = h;
            out[(size_t)T_STEPS * (BATCH * HID) + BATCH * HID + b * HID + j] = c;
        }

        __syncthreads();

        if (t < T_STEPS - 1) {
            if (tid == 0) {
                __threadfence();
                atomicAdd(&g_cnt[grp], 1u);
                const unsigned target = (unsigned)(t + 1) * CPG;
                while (ld_acq(&g_cnt[grp]) < target) { __nanosleep(32); }
            }
            __syncthreads();
        }
    }
}

// =======================================================================
// Launch
// =======================================================================
extern "C" void kernel_launch(void* const* d_in, const int* in_sizes, int n_in,
                              void* d_out, int out_size)
{
    const float* X  = (const float*)d_in[0];
    const float* Wf = (const float*)d_in[1];
    const float* bf = (const float*)d_in[2];
    const float* Wi = (const float*)d_in[3];
    const float* bi = (const float*)d_in[4];
    const float* Wg = (const float*)d_in[5];
    const float* bg = (const float*)d_in[6];
    const float* Wo = (const float*)d_in[7];
    const float* bo = (const float*)d_in[8];
    const float* qs = (const float*)d_in[9];
    const float* qb = (const float*)d_in[10];
    float* out = (float*)d_out;

    const int smem2 = (RPC * KP + BPG * KP + 8 * 1024 + 256) * (int)sizeof(float);
    cudaFuncSetAttribute(lstm_seq, cudaFuncAttributeMaxDynamicSharedMemorySize, smem2);
    cudaFuncSetAttribute(p1_mma, cudaFuncAttributeMaxDynamicSharedMemorySize, SMEM_P1);

    split_k<<<2048, 256>>>(X, Wf, Wi, Wg, Wo, bf, bi, bg, bo);
    p1_mma<<<dim3(G4 / 128, MROWS / 128), 256, SMEM_P1>>>();
    reset_k<<<1, 256>>>();
    lstm_seq<<<NCTA, 256, smem2>>>(Wf, Wi, Wg, Wo, qs, qb, out);
}

// round 4
// speedup vs baseline: 1.2760x; 1.2760x over previous
#include <cuda_runtime.h>
#include <cuda_bf16.h>
#include <cstdint>
#include <cstddef>

// Problem constants
#define T_STEPS 1024
#define BATCH   64
#define DIM     512
#define HID     512
#define DH      1024          // D + H
#define G4      2048          // 4*H
#define MROWS   (T_STEPS * BATCH)   // 65536

// Phase-2 partitioning
#define NGROUPS 4
#define CPG     32            // CTAs per group
#define NCTA    128
#define BPG     16            // batches per group
#define JPC     16            // hidden units per CTA
#define KPH     520           // padded h_s row stride (floats)

// ---------------- device scratch (static allocations only) ----------------
__device__ float    g_zx[(size_t)MROWS * G4];   // 512 MB precomputed x-part + bias
__device__ float    g_h[2][BATCH][HID];         // double-buffered hidden state
__device__ unsigned g_cnt[NGROUPS];             // per-group barrier counters

__device__ __forceinline__ unsigned ld_acq(unsigned* p) {
    unsigned v;
    asm volatile("ld.acquire.gpu.u32 %0, [%1];" : "=r"(v) : "l"(p) : "memory");
    return v;
}

// ---------------- packed fp32 helpers (sm_100+ base family) ----------------
__device__ __forceinline__ void fma2(unsigned long long& d, unsigned long long a,
                                     unsigned long long b) {
    asm("fma.rn.f32x2 %0, %1, %2, %0;" : "+l"(d) : "l"(a), "l"(b));
}
__device__ __forceinline__ unsigned long long pk2(float x, float y) {
    unsigned long long r;
    asm("mov.b64 %0, {%1, %2};" : "=l"(r) : "f"(x), "f"(y));
    return r;
}
__device__ __forceinline__ float2 unpk(unsigned long long v) {
    float2 r;
    asm("mov.b64 {%0, %1}, %2;" : "=f"(r.x), "=f"(r.y) : "l"(v));
    return r;
}

// =======================================================================
// Phase 1: Zx[m][gate*512+j] = x[m,:] . W_gate[j, 0:512] + b_gate[j]
// fp32x2 SGEMM, M=65536, N=2048, K=512. Tile 128x128, 256 threads, 8x8/thr.
// =======================================================================
#define KPAD 136
__global__ __launch_bounds__(256) void p1_gemm(
    const float* __restrict__ X,
    const float* __restrict__ Wf, const float* __restrict__ Wi,
    const float* __restrict__ Wg, const float* __restrict__ Wo,
    const float* __restrict__ bf, const float* __restrict__ bi,
    const float* __restrict__ bg, const float* __restrict__ bo)
{
    __shared__ float As[16][KPAD];
    __shared__ float Bs[16][KPAD];

    const int tid = threadIdx.x;
    const int m0  = blockIdx.y * 128;
    const int n0  = blockIdx.x * 128;
    const int gate = n0 >> 9;                    // 128 | 512 -> tile is gate-pure
    const float* Wsel = (gate == 0) ? Wf : (gate == 1) ? Wi : (gate == 2) ? Wg : Wo;
    const float* bsel = (gate == 0) ? bf : (gate == 1) ? bi : (gate == 2) ? bg : bo;
    const int jbase = n0 & 511;

    const int tm = tid & 15;      // 16 m-threads * 8 rows = 128
    const int tn = tid >> 4;      // 16 n-threads * 8 cols = 128

    unsigned long long acc2[4][8];
#pragma unroll
    for (int i = 0; i < 4; i++)
#pragma unroll
        for (int q = 0; q < 8; q++) acc2[i][q] = 0ull;

    for (int k0 = 0; k0 < 512; k0 += 16) {
        // A tile: 128 rows x 16 k  (512 float4, 2 per thread)
#pragma unroll
        for (int l = 0; l < 2; l++) {
            int lin = tid + l * 256;
            int row = lin >> 2, kc = lin & 3;
            float4 v = *(const float4*)&X[(size_t)(m0 + row) * 512 + k0 + kc * 4];
            As[kc * 4 + 0][row] = v.x;
            As[kc * 4 + 1][row] = v.y;
            As[kc * 4 + 2][row] = v.z;
            As[kc * 4 + 3][row] = v.w;
        }
        // B tile: 128 rows x 16 k (x-part of W: columns [0,512))
#pragma unroll
        for (int l = 0; l < 2; l++) {
            int lin = tid + l * 256;
            int row = lin >> 2, kc = lin & 3;
            float4 v = *(const float4*)&Wsel[(size_t)(jbase + row) * DH + k0 + kc * 4];
            Bs[kc * 4 + 0][row] = v.x;
            Bs[kc * 4 + 1][row] = v.y;
            Bs[kc * 4 + 2][row] = v.z;
            Bs[kc * 4 + 3][row] = v.w;
        }
        __syncthreads();

#pragma unroll
        for (int k = 0; k < 16; k++) {
            unsigned long long a2[4];
            a2[0] = *(const unsigned long long*)&As[k][tm * 8 + 0];
            a2[1] = *(const unsigned long long*)&As[k][tm * 8 + 2];
            a2[2] = *(const unsigned long long*)&As[k][tm * 8 + 4];
            a2[3] = *(const unsigned long long*)&As[k][tm * 8 + 6];
            float4 bv0 = *(const float4*)&Bs[k][tn * 8];
            float4 bv1 = *(const float4*)&Bs[k][tn * 8 + 4];
            unsigned long long b2[8];
            b2[0] = pk2(bv0.x, bv0.x); b2[1] = pk2(bv0.y, bv0.y);
            b2[2] = pk2(bv0.z, bv0.z); b2[3] = pk2(bv0.w, bv0.w);
            b2[4] = pk2(bv1.x, bv1.x); b2[5] = pk2(bv1.y, bv1.y);
            b2[6] = pk2(bv1.z, bv1.z); b2[7] = pk2(bv1.w, bv1.w);
#pragma unroll
            for (int i = 0; i < 4; i++)
#pragma unroll
                for (int q = 0; q < 8; q++) fma2(acc2[i][q], a2[i], b2[q]);
        }
        __syncthreads();
    }

    float bias[8];
#pragma unroll
    for (int q = 0; q < 8; q++) bias[q] = bsel[jbase + tn * 8 + q];

#pragma unroll
    for (int i2 = 0; i2 < 4; i2++) {
        const int mrow = m0 + tm * 8 + 2 * i2;
        float lo[8], hi[8];
#pragma unroll
        for (int q = 0; q < 8; q++) {
            float2 p = unpk(acc2[i2][q]);
            lo[q] = p.x + bias[q];
            hi[q] = p.y + bias[q];
        }
        float* r0 = &g_zx[(size_t)mrow * G4 + n0 + tn * 8];
        float* r1 = r0 + G4;
        *(float4*)r0       = make_float4(lo[0], lo[1], lo[2], lo[3]);
        *(float4*)(r0 + 4) = make_float4(lo[4], lo[5], lo[6], lo[7]);
        *(float4*)r1       = make_float4(hi[0], hi[1], hi[2], hi[3]);
        *(float4*)(r1 + 4) = make_float4(hi[4], hi[5], hi[6], hi[7]);
    }
}

// =======================================================================
// Reset kernel: zero barrier counters and h0 (deterministic per replay)
// =======================================================================
__global__ void reset_k()
{
    int tid = threadIdx.x;
    if (tid < NGROUPS) g_cnt[tid] = 0;
    float* p = &g_h[0][0][0];
    for (int i = tid; i < BATCH * HID; i += 256) p[i] = 0.f;
}

// =======================================================================
// Phase 2: persistent sequential LSTM. 128 CTAs (4 groups x 32), 256 thr.
// Recurrent weights resident in smem as interleaved row-PAIRS (f32x2
// operands), XOR-swizzled for conflict-free LDS.128.
//   pair p (0..31) holds rows 2p, 2p+1 (row rr = gate*16 + jl, 0..63).
//   owner thread rL = p & 7, j = p >> 3.
//   float2 for (pair p, k) stored at float offset:
//     p*1024 + ((g ^ (p&7)) << 2) + (k&1)*2   with g = k >> 1
// =======================================================================
#define SMEM2 ((32768 + 16 * KPH + 8192 + 256) * 4)

__global__ __launch_bounds__(256, 1) void lstm_seq(
    const float* __restrict__ Wf, const float* __restrict__ Wi,
    const float* __restrict__ Wg, const float* __restrict__ Wo,
    const float* __restrict__ q_scale, const float* __restrict__ q_bias,
    float* __restrict__ out)
{
    extern __shared__ float smf[];
    float* wp_s = smf;                                   // 32768 floats (128KB)
    float* h_s  = smf + 32768;                           // 16*KPH
    unsigned long long* red2 = (unsigned long long*)(smf + 32768 + 16 * KPH); // 4096 u64
    float* c_s = (float*)(red2 + 4096);                  // 256

    const int tid = threadIdx.x;
    const int cta = blockIdx.x;
    const int grp = cta >> 5;
    const int cig = cta & 31;
    const int b0  = grp * BPG;
    const int j0  = cig * JPC;

    // Load recurrent weights (columns [512,1024)) into paired+swizzled layout.
    for (int idx = tid; idx < 64 * 512; idx += 256) {
        int rr = idx >> 9, k = idx & 511;
        int gate = rr >> 4, jl_ = rr & 15;
        const float* wpt = (gate == 0) ? Wf : (gate == 1) ? Wi : (gate == 2) ? Wg : Wo;
        float v = wpt[(size_t)(j0 + jl_) * DH + 512 + k];
        int p = rr >> 1, half = rr & 1, g = k >> 1, ko = k & 1;
        wp_s[p * 1024 + ((g ^ (p & 7)) << 2) + ko * 2 + half] = v;
    }
    c_s[tid] = 0.f;

    const int jl = tid & 15, bl = tid >> 4;
    const int j = j0 + jl, b = b0 + bl;
    const float qs = q_scale[j], qb = q_bias[j];

    const int lane = tid & 31, wrp = tid >> 5;
    const int rL = lane & 7, bL = lane >> 3;
    const int kbase = wrp * 64;
    const int uB = bl >> 2, bLL = bl & 3;
    const float* wthr = wp_s + rL * 1024;
    float* redf = (float*)red2;

    __syncthreads();

    for (int t = 0; t < T_STEPS; t++) {
        // ---- prefetch Zx operand for this (t, b, j) early (hide DRAM) ----
        const float* zxp = &g_zx[((size_t)(t * BATCH + b)) * G4 + j];
        float zpre[4];
#pragma unroll
        for (int gate = 0; gate < 4; gate++) zpre[gate] = __ldcg(zxp + gate * 512);

        // ---- stage h_t for this group's 16 batches (L2 -> smem) ----
        const float* hsrc = &g_h[t & 1][b0][0];
        for (int i = tid; i < BPG * 128; i += 256) {
            int row = i >> 7, c4 = i & 127;
            float4 v = __ldcg((const float4*)(hsrc + row * 512 + c4 * 4));
            *(float4*)&h_s[row * KPH + c4 * 4] = v;
        }
        __syncthreads();

        // ---- packed GEMM: warp owns K-chunk of 64; 16 batch x 8 row-pairs ----
        unsigned long long acc2[4][4];
#pragma unroll
        for (int u = 0; u < 4; u++)
#pragma unroll
            for (int jj = 0; jj < 4; jj++) acc2[u][jj] = 0ull;

#pragma unroll 4
        for (int kk = 0; kk < 64; kk += 4) {
            const int k = kbase + kk;
            const int g0 = k >> 1;                       // even
            const int s0 = ((g0 ^ rL) << 2);
            const int s1 = (((g0 + 1) ^ rL) << 2);

            unsigned long long hp[4][4];
#pragma unroll
            for (int u = 0; u < 4; u++) {
                float4 hv = *(const float4*)&h_s[(bL + 4 * u) * KPH + k];
                hp[u][0] = pk2(hv.x, hv.x);
                hp[u][1] = pk2(hv.y, hv.y);
                hp[u][2] = pk2(hv.z, hv.z);
                hp[u][3] = pk2(hv.w, hv.w);
            }
#pragma unroll
            for (int jj = 0; jj < 4; jj++) {
                const float* wj = wthr + jj * 8192;
                ulonglong2 wA = *(const ulonglong2*)(wj + s0);   // k, k+1
                ulonglong2 wB = *(const ulonglong2*)(wj + s1);   // k+2, k+3
#pragma unroll
                for (int u = 0; u < 4; u++) {
                    fma2(acc2[u][jj], hp[u][0], wA.x);
                    fma2(acc2[u][jj], hp[u][1], wA.y);
                    fma2(acc2[u][jj], hp[u][2], wB.x);
                    fma2(acc2[u][jj], hp[u][3], wB.y);
                }
            }
        }

        // ---- write packed partials ----
#pragma unroll
        for (int u = 0; u < 4; u++)
#pragma unroll
            for (int jj = 0; jj < 4; jj++)
                red2[wrp * 512 + (u * 4 + jj) * 32 + rL * 4 + bL] = acc2[u][jj];
        __syncthreads();

        // ---- reduce across 8 warps, add Zx, gates, state update ----
        float z[4];
#pragma unroll
        for (int gate = 0; gate < 4; gate++) {
            int r = gate * 16 + jl;
            int p = r >> 1;
            int idx = ((uB * 4 + (p >> 3)) * 32 + (p & 7) * 4 + bLL) * 2 + (r & 1);
            float s = 0.f;
#pragma unroll
            for (int ww = 0; ww < 8; ww++) s += redf[ww * 1024 + idx];
            z[gate] = s + zpre[gate];
        }

        float sf = 1.f / (1.f + expf(-z[0]));
        float si = 1.f / (1.f + expf(-z[1]));
        float sg = tanhf(z[2]);
        float so = 1.f / (1.f + expf(-z[3]));

        float fg = tanhf(sf * qs + qb);
        float ig = tanhf(si * qs + qb);
        float gg = tanhf(sg * qs + qb);
        float og = tanhf(so * qs + qb);

        float c = fg * c_s[tid] + ig * gg;
        c_s[tid] = c;
        float h = og * tanhf(c);

        g_h[(t + 1) & 1][b][j] = h;
        out[(size_t)t * (BATCH * HID) + b * HID + j] = h;
        if (t == T_STEPS - 1) {
            out[(size_t)T_STEPS * (BATCH * HID) + b * HID + j] = h;                 // hx
            out[(size_t)T_STEPS * (BATCH * HID) + BATCH * HID + b * HID + j] = c;   // cx
        }

        __syncthreads();   // all threads done writing h before arrival

        if (t < T_STEPS - 1) {
            if (tid == 0) {
                __threadfence();
                atomicAdd(&g_cnt[grp], 1u);
                const unsigned target = (unsigned)(t + 1) * CPG;
                while (ld_acq(&g_cnt[grp]) < target) { __nanosleep(32); }
            }
            __syncthreads();
        }
    }
}

// =======================================================================
// Launch
// =======================================================================
extern "C" void kernel_launch(void* const* d_in, const int* in_sizes, int n_in,
                              void* d_out, int out_size)
{
    const float* X  = (const float*)d_in[0];
    const float* Wf = (const float*)d_in[1];
    const float* bf = (const float*)d_in[2];
    const float* Wi = (const float*)d_in[3];
    const float* bi = (const float*)d_in[4];
    const float* Wg = (const float*)d_in[5];
    const float* bg = (const float*)d_in[6];
    const float* Wo = (const float*)d_in[7];
    const float* bo = (const float*)d_in[8];
    const float* qs = (const float*)d_in[9];
    const float* qb = (const float*)d_in[10];
    float* out = (float*)d_out;

    cudaFuncSetAttribute(lstm_seq, cudaFuncAttributeMaxDynamicSharedMemorySize, SMEM2);

    p1_gemm<<<dim3(G4 / 128, MROWS / 128), 256>>>(X, Wf, Wi, Wg, Wo, bf, bi, bg, bo);
    reset_k<<<1, 256>>>();
    lstm_seq<<<NCTA, 256, SMEM2>>>(Wf, Wi, Wg, Wo, qs, qb, out);
}

// round 5
// speedup vs baseline: 1.4597x; 1.1439x over previous
#include <cuda_runtime.h>
#include <cuda_bf16.h>
#include <cstdint>
#include <cstddef>

// Problem constants
#define T_STEPS 1024
#define BATCH   64
#define DIM     512
#define HID     512
#define DH      1024          // D + H
#define G4      2048          // 4*H
#define MROWS   (T_STEPS * BATCH)   // 65536

// Phase-2 partitioning
#define NGROUPS 4
#define CPG     32            // CTAs per group
#define NCTA    128
#define BPG     16            // batches per group
#define JPC     16            // hidden units per CTA
#define KPH     520           // padded h_s row stride (floats)

// ---------------- device scratch (static allocations only) ----------------
__device__ float    g_zx[(size_t)MROWS * G4];   // 512 MB precomputed x-part + bias
__device__ float    g_h[2][BATCH][HID];         // double-buffered hidden state
__device__ unsigned g_cnt[NGROUPS];             // per-group barrier counters

__device__ __forceinline__ unsigned ld_acq(unsigned* p) {
    unsigned v;
    asm volatile("ld.acquire.gpu.u32 %0, [%1];" : "=r"(v) : "l"(p) : "memory");
    return v;
}

// ---------------- packed fp32 helpers (FFMA2 on sm_103) ----------------
__device__ __forceinline__ void fma2(unsigned long long& d, unsigned long long a,
                                     unsigned long long b) {
    asm("fma.rn.f32x2 %0, %1, %2, %0;" : "+l"(d) : "l"(a), "l"(b));
}
__device__ __forceinline__ unsigned long long pk2(float x, float y) {
    unsigned long long r;
    asm("mov.b64 %0, {%1, %2};" : "=l"(r) : "f"(x), "f"(y));
    return r;
}
__device__ __forceinline__ float2 unpk(unsigned long long v) {
    float2 r;
    asm("mov.b64 {%0, %1}, %2;" : "=f"(r.x), "=f"(r.y) : "l"(v));
    return r;
}

// ---------------- fast transcendentals (|.|-guarded, err ~1e-6) ----------------
__device__ __forceinline__ float fsig(float z) {
    float e = __expf(-fabsf(z));
    float r = __fdividef(1.f, 1.f + e);        // sigma(|z|)
    return z >= 0.f ? r : 1.f - r;
}
__device__ __forceinline__ float ftanh(float z) {
    float e = __expf(-2.f * fabsf(z));
    float r = __fdividef(1.f - e, 1.f + e);    // tanh(|z|), safe for any |z|
    return copysignf(r, z);
}

// ---------------- cp.async helpers ----------------
__device__ __forceinline__ uint32_t smem_u32(const void* p) {
    uint32_t a;
    asm("{ .reg .u64 t; cvta.to.shared.u64 t, %1; cvt.u32.u64 %0, t; }" : "=r"(a) : "l"(p));
    return a;
}
__device__ __forceinline__ void cp16(uint32_t dst, const void* src) {
    asm volatile("cp.async.cg.shared.global [%0], [%1], 16;" :: "r"(dst), "l"(src));
}
__device__ __forceinline__ void cp_commit() { asm volatile("cp.async.commit_group;" ::: "memory"); }
__device__ __forceinline__ void cp_wait0() {
    asm volatile("cp.async.wait_group 0;" ::: "memory");
}

// =======================================================================
// Phase 1: Zx[m][gate*512+j] = x[m,:] . W_gate[j, 0:512] + b_gate[j]
// fp32x2 SGEMM, tile 128x128, 256 threads, 8x8/thread.
// Acc pairs along m at stride 32: pair p covers rows (32p + 2tm, +1)
//   -> A LDS.64 lane-contiguous (conflict-free), B broadcast.
// =======================================================================
#define KPAD 132
__global__ __launch_bounds__(256) void p1_gemm(
    const float* __restrict__ X,
    const float* __restrict__ Wf, const float* __restrict__ Wi,
    const float* __restrict__ Wg, const float* __restrict__ Wo,
    const float* __restrict__ bf, const float* __restrict__ bi,
    const float* __restrict__ bg, const float* __restrict__ bo)
{
    __shared__ float As[16][KPAD];
    __shared__ float Bs[16][KPAD];

    const int tid = threadIdx.x;
    const int m0  = blockIdx.y * 128;
    const int n0  = blockIdx.x * 128;
    const int gate = n0 >> 9;                    // tile is gate-pure
    const float* Wsel = (gate == 0) ? Wf : (gate == 1) ? Wi : (gate == 2) ? Wg : Wo;
    const float* bsel = (gate == 0) ? bf : (gate == 1) ? bi : (gate == 2) ? bg : bo;
    const int jbase = n0 & 511;

    const int tm = tid & 15;      // 16 m-threads; pair p -> rows 32p + 2tm (+1)
    const int tn = tid >> 4;      // 16 n-threads * 8 cols = 128

    unsigned long long acc2[4][8];
#pragma unroll
    for (int i = 0; i < 4; i++)
#pragma unroll
        for (int q = 0; q < 8; q++) acc2[i][q] = 0ull;

    for (int k0 = 0; k0 < 512; k0 += 16) {
        // A tile: 128 rows x 16 k  (transposed to [k][m])
#pragma unroll
        for (int l = 0; l < 2; l++) {
            int lin = tid + l * 256;
            int row = lin >> 2, kc = lin & 3;
            float4 v = *(const float4*)&X[(size_t)(m0 + row) * 512 + k0 + kc * 4];
            As[kc * 4 + 0][row] = v.x;
            As[kc * 4 + 1][row] = v.y;
            As[kc * 4 + 2][row] = v.z;
            As[kc * 4 + 3][row] = v.w;
        }
        // B tile: 128 rows x 16 k
#pragma unroll
        for (int l = 0; l < 2; l++) {
            int lin = tid + l * 256;
            int row = lin >> 2, kc = lin & 3;
            float4 v = *(const float4*)&Wsel[(size_t)(jbase + row) * DH + k0 + kc * 4];
            Bs[kc * 4 + 0][row] = v.x;
            Bs[kc * 4 + 1][row] = v.y;
            Bs[kc * 4 + 2][row] = v.z;
            Bs[kc * 4 + 3][row] = v.w;
        }
        __syncthreads();

#pragma unroll
        for (int k = 0; k < 16; k++) {
            unsigned long long a2[4];
#pragma unroll
            for (int p = 0; p < 4; p++)
                a2[p] = *(const unsigned long long*)&As[k][32 * p + 2 * tm];
            float4 bv0 = *(const float4*)&Bs[k][tn * 8];
            float4 bv1 = *(const float4*)&Bs[k][tn * 8 + 4];
            unsigned long long b2[8];
            b2[0] = pk2(bv0.x, bv0.x); b2[1] = pk2(bv0.y, bv0.y);
            b2[2] = pk2(bv0.z, bv0.z); b2[3] = pk2(bv0.w, bv0.w);
            b2[4] = pk2(bv1.x, bv1.x); b2[5] = pk2(bv1.y, bv1.y);
            b2[6] = pk2(bv1.z, bv1.z); b2[7] = pk2(bv1.w, bv1.w);
#pragma unroll
            for (int p = 0; p < 4; p++)
#pragma unroll
                for (int q = 0; q < 8; q++) fma2(acc2[p][q], a2[p], b2[q]);
        }
        __syncthreads();
    }

    float bias[8];
#pragma unroll
    for (int q = 0; q < 8; q++) bias[q] = bsel[jbase + tn * 8 + q];

#pragma unroll
    for (int p = 0; p < 4; p++) {
        const int mrow = m0 + 32 * p + 2 * tm;
        float lo[8], hi[8];
#pragma unroll
        for (int q = 0; q < 8; q++) {
            float2 v = unpk(acc2[p][q]);
            lo[q] = v.x + bias[q];
            hi[q] = v.y + bias[q];
        }
        float* r0 = &g_zx[(size_t)mrow * G4 + n0 + tn * 8];
        float* r1 = r0 + G4;
        *(float4*)r0       = make_float4(lo[0], lo[1], lo[2], lo[3]);
        *(float4*)(r0 + 4) = make_float4(lo[4], lo[5], lo[6], lo[7]);
        *(float4*)r1       = make_float4(hi[0], hi[1], hi[2], hi[3]);
        *(float4*)(r1 + 4) = make_float4(hi[4], hi[5], hi[6], hi[7]);
    }
}

// =======================================================================
// Reset kernel: zero barrier counters and h0 (deterministic per replay)
// =======================================================================
__global__ void reset_k()
{
    int tid = threadIdx.x;
    if (tid < NGROUPS) g_cnt[tid] = 0;
    float* p = &g_h[0][0][0];
    for (int i = tid; i < BATCH * HID; i += 256) p[i] = 0.f;
}

// =======================================================================
// Phase 2: persistent sequential LSTM. 128 CTAs (4 groups x 32), 256 thr.
// Weights resident in smem as interleaved row-pairs, XOR-swizzled.
// =======================================================================
#define SMEM2 ((32768 + 16 * KPH + 8192) * 4)

__global__ __launch_bounds__(256, 1) void lstm_seq(
    const float* __restrict__ Wf, const float* __restrict__ Wi,
    const float* __restrict__ Wg, const float* __restrict__ Wo,
    const float* __restrict__ q_scale, const float* __restrict__ q_bias,
    float* __restrict__ out)
{
    extern __shared__ float smf[];
    float* wp_s = smf;                                   // 32768 floats (128KB)
    float* h_s  = smf + 32768;                           // 16*KPH
    unsigned long long* red2 = (unsigned long long*)(smf + 32768 + 16 * KPH); // 4096 u64

    const int tid = threadIdx.x;
    const int cta = blockIdx.x;
    const int grp = cta >> 5;
    const int cig = cta & 31;
    const int b0  = grp * BPG;
    const int j0  = cig * JPC;

    // Load recurrent weights (columns [512,1024)) into paired+swizzled layout.
    for (int idx = tid; idx < 64 * 512; idx += 256) {
        int rr = idx >> 9, k = idx & 511;
        int gate = rr >> 4, jl_ = rr & 15;
        const float* wpt = (gate == 0) ? Wf : (gate == 1) ? Wi : (gate == 2) ? Wg : Wo;
        float v = wpt[(size_t)(j0 + jl_) * DH + 512 + k];
        int p = rr >> 1, half = rr & 1, g = k >> 1, ko = k & 1;
        wp_s[p * 1024 + ((g ^ (p & 7)) << 2) + ko * 2 + half] = v;
    }

    const int jl = tid & 15, bl = tid >> 4;
    const int j = j0 + jl, b = b0 + bl;
    const float qs = q_scale[j], qb = q_bias[j];

    const int lane = tid & 31, wrp = tid >> 5;
    const int rL = lane & 7, bL = lane >> 3;
    const int kbase = wrp * 64;
    const int uB = bl >> 2, bLL = bl & 3;
    const float* wthr = wp_s + rL * 1024;
    float* redf = (float*)red2;
    const uint32_t hs_base = smem_u32(h_s);

    float creg = 0.f;
    __syncthreads();

    for (int t = 0; t < T_STEPS; t++) {
        // ---- prefetch Zx operand for this (t, b, j) early (DRAM latency) ----
        const float* zxp = &g_zx[((size_t)(t * BATCH + b)) * G4 + j];
        float zpre[4];
#pragma unroll
        for (int gate = 0; gate < 4; gate++) zpre[gate] = __ldcg(zxp + gate * 512);

        // ---- stage h_t for this group's 16 batches (L2 -> smem, cp.async) ----
        const float* hsrc = &g_h[t & 1][b0][0];
#pragma unroll
        for (int l = 0; l < 8; l++) {
            int i = tid + l * 256;
            int row = i >> 7, c4 = i & 127;
            cp16(hs_base + (uint32_t)(row * KPH + c4 * 4) * 4u, hsrc + row * 512 + c4 * 4);
        }
        cp_commit();
        cp_wait0();
        __syncthreads();

        // ---- packed GEMM: warp owns K-chunk of 64; 16 batch x 8 row-pairs ----
        unsigned long long acc2[4][4];
#pragma unroll
        for (int u = 0; u < 4; u++)
#pragma unroll
            for (int jj = 0; jj < 4; jj++) acc2[u][jj] = 0ull;

#pragma unroll 4
        for (int kk = 0; kk < 64; kk += 4) {
            const int k = kbase + kk;
            const int g0 = k >> 1;                       // even
            const int s0 = ((g0 ^ rL) << 2);
            const int s1 = (((g0 + 1) ^ rL) << 2);

            unsigned long long hp[4][4];
#pragma unroll
            for (int u = 0; u < 4; u++) {
                float4 hv = *(const float4*)&h_s[(bL + 4 * u) * KPH + k];
                hp[u][0] = pk2(hv.x, hv.x);
                hp[u][1] = pk2(hv.y, hv.y);
                hp[u][2] = pk2(hv.z, hv.z);
                hp[u][3] = pk2(hv.w, hv.w);
            }
#pragma unroll
            for (int jj = 0; jj < 4; jj++) {
                const float* wj = wthr + jj * 8192;
                ulonglong2 wA = *(const ulonglong2*)(wj + s0);   // k, k+1
                ulonglong2 wB = *(const ulonglong2*)(wj + s1);   // k+2, k+3
#pragma unroll
                for (int u = 0; u < 4; u++) {
                    fma2(acc2[u][jj], hp[u][0], wA.x);
                    fma2(acc2[u][jj], hp[u][1], wA.y);
                    fma2(acc2[u][jj], hp[u][2], wB.x);
                    fma2(acc2[u][jj], hp[u][3], wB.y);
                }
            }
        }

        // ---- write packed partials ----
#pragma unroll
        for (int u = 0; u < 4; u++)
#pragma unroll
            for (int jj = 0; jj < 4; jj++)
                red2[wrp * 512 + (u * 4 + jj) * 32 + rL * 4 + bL] = acc2[u][jj];
        __syncthreads();

        // ---- reduce across 8 warps, add Zx, gates, state update ----
        float z[4];
#pragma unroll
        for (int gate = 0; gate < 4; gate++) {
            int r = gate * 16 + jl;
            int p = r >> 1;
            int idx = ((uB * 4 + (p >> 3)) * 32 + (p & 7) * 4 + bLL) * 2 + (r & 1);
            float s = 0.f;
#pragma unroll
            for (int ww = 0; ww < 8; ww++) s += redf[ww * 1024 + idx];
            z[gate] = s + zpre[gate];
        }

        float fg = ftanh(fsig(z[0]) * qs + qb);
        float ig = ftanh(fsig(z[1]) * qs + qb);
        float gg = ftanh(ftanh(z[2]) * qs + qb);
        float og = ftanh(fsig(z[3]) * qs + qb);

        float c = fg * creg + ig * gg;
        creg = c;
        float h = og * ftanh(c);

        g_h[(t + 1) & 1][b][j] = h;
        __syncthreads();              // all h stores done CTA-wide

        // arrive early: overlap out[] stores with peers' arrivals
        if (t < T_STEPS - 1 && tid == 0) {
            __threadfence();
            atomicAdd(&g_cnt[grp], 1u);
        }

        out[(size_t)t * (BATCH * HID) + b * HID + j] = h;
        if (t == T_STEPS - 1) {
            out[(size_t)T_STEPS * (BATCH * HID) + b * HID + j] = h;                 // hx
            out[(size_t)T_STEPS * (BATCH * HID) + BATCH * HID + b * HID + j] = c;   // cx
        }

        if (t < T_STEPS - 1) {
            if (tid == 0) {
                const unsigned target = (unsigned)(t + 1) * CPG;
                while (ld_acq(&g_cnt[grp]) < target) { __nanosleep(16); }
            }
            __syncthreads();
        }
    }
}

// =======================================================================
// Launch
// =======================================================================
extern "C" void kernel_launch(void* const* d_in, const int* in_sizes, int n_in,
                              void* d_out, int out_size)
{
    const float* X  = (const float*)d_in[0];
    const float* Wf = (const float*)d_in[1];
    const float* bf = (const float*)d_in[2];
    const float* Wi = (const float*)d_in[3];
    const float* bi = (const float*)d_in[4];
    const float* Wg = (const float*)d_in[5];
    const float* bg = (const float*)d_in[6];
    const float* Wo = (const float*)d_in[7];
    const float* bo = (const float*)d_in[8];
    const float* qs = (const float*)d_in[9];
    const float* qb = (const float*)d_in[10];
    float* out = (float*)d_out;

    cudaFuncSetAttribute(lstm_seq, cudaFuncAttributeMaxDynamicSharedMemorySize, SMEM2);

    p1_gemm<<<dim3(G4 / 128, MROWS / 128), 256>>>(X, Wf, Wi, Wg, Wo, bf, bi, bg, bo);
    reset_k<<<1, 256>>>();
    lstm_seq<<<NCTA, 256, SMEM2>>>(Wf, Wi, Wg, Wo, qs, qb, out);
}